// round 16
// baseline (speedup 1.0000x reference)
#include <cuda_runtime.h>
#include <cuda_bf16.h>
#include <math.h>

#define Hh 2
#define Bb 8
#define Nn 2048
#define Dd 64
#define Qq 16
#define Cc 129
#define C8v 16
#define Kk 8192
#define VP 136
#define NEGV (-9.0e15f)
#define NROW (Bb*Nn)
#define RT 64
#define MT 64
#define NTILE (Nn/MT)
#define NT_C 17

typedef unsigned long long u64t;
typedef unsigned u32t;

// bf16 mma
#define MMA_BF16(c0,c1,c2,c3, a0,a1,a2,a3, b0,b1) \
    asm volatile("mma.sync.aligned.m16n8k16.row.col.f32.bf16.bf16.f32 " \
        "{%0,%1,%2,%3}, {%4,%5,%6,%7}, {%8,%9}, {%0,%1,%2,%3};" \
        : "+f"(c0), "+f"(c1), "+f"(c2), "+f"(c3) \
        : "r"(a0), "r"(a1), "r"(a2), "r"(a3), "r"(b0), "r"(b1))

// ---------------- device scratch ----------------
__device__ float g_q[Hh*NROW*C8v];
__device__ float g_k[Hh*NROW*C8v];
__device__ u32t  g_vt_hi[Hh*136*(NROW/2)];
__device__ u32t  g_vt_lo[Hh*136*(NROW/2)];
__device__ float g_comb[NROW*VP];
__device__ float g_u[Kk*Dd];
__device__ float g_hsel[Kk*Dd];
__device__ float g_cx[Kk*Dd];
__device__ int   g_batch_flag[Bb];
__device__ int   g_tile_flag[NROW/RT];
__device__ u32t  g_Wt_hi[4*16*64*64];
__device__ u32t  g_Wt_lo[4*16*64*64];
__device__ float g_Ws[4*16*64];

// ---------------- cp.async helpers ----------------
__device__ __forceinline__ unsigned smem_u32(const void* p) {
    return (unsigned)__cvta_generic_to_shared(p);
}
__device__ __forceinline__ void cp16(void* dst, const void* src) {
    asm volatile("cp.async.cg.shared.global [%0], [%1], 16;\n"
                 :: "r"(smem_u32(dst)), "l"(src));
}
__device__ __forceinline__ void cp_commit() { asm volatile("cp.async.commit_group;\n"); }
template<int N> __device__ __forceinline__ void cp_wait() {
    asm volatile("cp.async.wait_group %0;\n" :: "n"(N));
}

// ---------------- flags ----------------
__global__ void flag_zero_kernel() {
    int t = threadIdx.x;
    if (t < Bb) g_batch_flag[t] = 0;
    for (int i = t; i < NROW/RT; i += 256) g_tile_flag[i] = 0;
}
__global__ void flag_mark_kernel(const int* __restrict__ nodes) {
    int i = blockIdx.x * 256 + threadIdx.x;
    if (i < Kk) {
        int row = nodes[i];
        g_tile_flag[row >> 6] = 1;
        g_batch_flag[row >> 11] = 1;
    }
}

// ---------------- weight split ----------------
__global__ void wsplit_kernel(const float* __restrict__ W_r,
                              const float* __restrict__ W_u,
                              const float* __restrict__ W_c) {
    const int q = blockIdx.x, s = blockIdx.y, t = threadIdx.x;
    const float* W = (s == 0) ? W_r : (s == 1) ? W_u : W_c;
    const int rb0 = (s == 3) ? 65 : 0;
    const int npair = (s < 2) ? 64 : 32;
    const int srow = (s < 2) ? 128 : (s == 2) ? 64 : -1;
    for (int idx = t; idx < 64 * 64; idx += 256) {
        int o = idx >> 6, kp = idx & 63;
        float v0 = 0.f, v1 = 0.f;
        if (kp < npair) {
            int k0 = rb0 + 2 * kp;
            v0 = W[(q * Cc + k0) * 64 + o];
            v1 = W[(q * Cc + k0 + 1) * 64 + o];
        }
        __nv_bfloat162 h2 = __floats2bfloat162_rn(v0, v1);
        __nv_bfloat162 l2 = __floats2bfloat162_rn(
            v0 - __bfloat162float(h2.x), v1 - __bfloat162float(h2.y));
        size_t gi = ((size_t)(s * 16 + q) * 64 + o) * 64 + kp;
        g_Wt_hi[gi] = *reinterpret_cast<u32t*>(&h2);
        g_Wt_lo[gi] = *reinterpret_cast<u32t*>(&l2);
    }
    if (srow >= 0) {
        for (int o = t; o < 64; o += 256)
            g_Ws[(s * 16 + q) * 64 + o] = W[(q * Cc + srow) * 64 + o];
    }
}

// =================== 1) QKV projection (W amortized over 4 row subtiles) ===================
struct ProjSmem {
    union {
        float comb[Cc][36];
        struct { __nv_bfloat16 hi[136][32]; __nv_bfloat16 lo[136][32]; } st;
    } u;
    float W[Cc][VP];
    float bias[VP];
};

__global__ void proj_kernel(const float* __restrict__ x, const float* __restrict__ h,
                            const float* __restrict__ Wq, const float* __restrict__ bq,
                            const float* __restrict__ Wk, const float* __restrict__ bk,
                            const float* __restrict__ Wv, const float* __restrict__ bv) {
    extern __shared__ char sm_raw[];
    ProjSmem& sm = *reinterpret_cast<ProjSmem*>(sm_raw);
    const int t = threadIdx.x;
    const int row_base = blockIdx.x * 128;
    if (!g_batch_flag[row_base >> 11]) return;
    const int y = blockIdx.y;

    // ---- load W + bias ONCE ----
    if (y == 0) {
        for (int idx = t; idx < Cc * 64; idx += 256) {
            int c = idx / 64, o = idx % 64;
            float w;
            if (o < 32)      w = Wq[((o >> 4) * Cc + c) * C8v + (o & 15)];
            else { int o2 = o - 32; w = Wk[((o2 >> 4) * Cc + c) * C8v + (o2 & 15)]; }
            sm.W[c][o] = w;
        }
        if (t < 64) {
            float b;
            if (t < 32)      b = bq[(t >> 4) * C8v + (t & 15)];
            else { int o2 = t - 32; b = bk[(o2 >> 4) * C8v + (o2 & 15)]; }
            sm.bias[t] = b;
        }
    } else {
        int hh = y - 1;
        for (int idx = t; idx < Cc * VP; idx += 256) {
            int c = idx / VP, o = idx % VP;
            sm.W[c][o] = (o < Cc) ? Wv[(hh * Cc + c) * Cc + o] : 0.f;
        }
        for (int o = t; o < VP; o += 256) sm.bias[o] = (o < Cc) ? bv[hh * Cc + o] : 0.f;
    }

    for (int st = 0; st < 4; st++) {
        const int row0 = row_base + st * 32;
        __syncthreads();   // prior subtile's reads of comb/staging done; W visible on st=0

        for (int idx = t; idx < 32 * Cc; idx += 256) {
            int r = idx / Cc, c = idx % Cc;
            int row = row0 + r;
            float v = (c < 65) ? x[row * 65 + c] : h[row * 64 + (c - 65)];
            sm.u.comb[c][r] = v;
        }
        __syncthreads();

        if (y == 0) {
            int r = t >> 3, og = t & 7;
            int c0 = og * 8;
            float acc[8];
#pragma unroll
            for (int j = 0; j < 8; j++) acc[j] = 0.f;
            for (int c = 0; c < Cc; c++) {
                float a = sm.u.comb[c][r];
#pragma unroll
                for (int j = 0; j < 8; j++) acc[j] += a * sm.W[c][c0 + j];
            }
            int row = row0 + r;
#pragma unroll
            for (int j = 0; j < 8; j++) {
                int o = c0 + j;
                float val = acc[j] + sm.bias[o];
                if (o < 32) {
                    g_q[(((o >> 4) * NROW) + row) * C8v + (o & 15)] = val;
                } else {
                    int o2 = o - 32;
                    g_k[(((o2 >> 4) * NROW) + row) * C8v + (o2 & 15)] = val;
                }
            }
        } else {
            int hh = y - 1;
            int r = t >> 3, og = t & 7;
            int c0 = og * 16;
            int xcol = 128 + og;
            float acc[17];
#pragma unroll
            for (int j = 0; j < 17; j++) acc[j] = 0.f;
            for (int c = 0; c < Cc; c++) {
                float a = sm.u.comb[c][r];
#pragma unroll
                for (int j = 0; j < 16; j++) acc[j] += a * sm.W[c][c0 + j];
                acc[16] += a * sm.W[c][xcol];
            }
            __syncthreads();   // comb dead; staging aliases it
#pragma unroll
            for (int j = 0; j < 17; j++) {
                int c = (j < 16) ? (c0 + j) : xcol;
                float val = acc[j] + sm.bias[c];
                __nv_bfloat16 bh = __float2bfloat16(val);
                sm.u.st.hi[c][r] = bh;
                sm.u.st.lo[c][r] = __float2bfloat16(val - __bfloat162float(bh));
            }
            __syncthreads();
            for (int idx = t; idx < 136 * 16; idx += 256) {
                int c = idx >> 4, w = idx & 15;
                size_t gi = (size_t)(hh * 136 + c) * (NROW / 2) + (row0 >> 1) + w;
                g_vt_hi[gi] = ((const u32t*)&sm.u.st.hi[c][0])[w];
                g_vt_lo[gi] = ((const u32t*)&sm.u.st.lo[c][0])[w];
            }
        }
    }
}

// =================== 2) attention (R10/R15, unchanged) ===================
struct AttnSmem {
    u32t  vt[2][Hh][136][68];
    float k[Hh][MT][C8v];
    float p[Hh][MT][RT];
    u32t  p_hi[Hh][RT][36];
    u32t  p_lo[Hh][RT][36];
    float rmax[Hh][RT];
    float rsum[Hh][RT];
    float fac[Hh][RT];
};

__device__ __forceinline__ void attn_prefetch_vt(AttnSmem& sm, int buf, int b,
                                                 int m0, int t) {
    const int half = (b * Nn + m0) >> 1;
    for (int idx = t; idx < Hh * 136 * 8; idx += 256) {
        int h_ = idx / (136 * 8), rem = idx % (136 * 8), c = rem >> 3, w4 = rem & 7;
        size_t gi = (size_t)(h_ * 136 + c) * (NROW / 2) + half + w4 * 4;
        cp16(&sm.vt[buf][h_][c][w4 * 4], &g_vt_hi[gi]);
        cp16(&sm.vt[buf][h_][c][32 + w4 * 4], &g_vt_lo[gi]);
    }
}
__device__ __forceinline__ void attn_prefetch_k(AttnSmem& sm, int b, int m0, int t) {
    for (int idx = t; idx < Hh * MT * 4; idx += 256) {
        int h_ = idx / (MT * 4), rem = idx % (MT * 4), m = rem >> 2, d4 = rem & 3;
        cp16(&sm.k[h_][m][d4 * 4],
             &g_k[((h_ * NROW) + b * Nn + m0 + m) * C8v + d4 * 4]);
    }
}

__global__ void __launch_bounds__(256, 1) attn_kernel(const int* __restrict__ adjg) {
    extern __shared__ char sm_raw[];
    AttnSmem& sm = *reinterpret_cast<AttnSmem*>(sm_raw);
    const int t = threadIdx.x;
    const int b = blockIdx.y;
    const int row0 = blockIdx.x * RT;
    if (!g_tile_flag[(b * Nn + row0) >> 6]) return;

    const int s_hh = t >> 7, s_r = (t & 127) >> 1, s_half = t & 1;
    const int warp = t >> 5, lane = t & 31;
    const int m_h = warp >> 2;
    const int m_R0 = (warp & 3) * 16;
    const int gid = lane >> 2, tg = lane & 3;
    const int x_hh = t >> 6, x_r = t & 63;
    const int ra = m_R0 + gid, rb = m_R0 + gid + 8;

    float qreg[16];
    {
        const float4* qsrc = (const float4*)&g_q[((s_hh * NROW) + b * Nn + row0 + s_r) * C8v];
#pragma unroll
        for (int j = 0; j < 4; j++) {
            float4 qq = qsrc[j];
            qreg[4 * j] = qq.x; qreg[4 * j + 1] = qq.y;
            qreg[4 * j + 2] = qq.z; qreg[4 * j + 3] = qq.w;
        }
    }
    if (t < 128) { sm.rmax[x_hh][x_r] = -INFINITY; sm.rsum[x_hh][x_r] = 0.f; }

    float acc[NT_C][4];
#pragma unroll
    for (int n = 0; n < NT_C; n++)
#pragma unroll
        for (int j = 0; j < 4; j++) acc[n][j] = 0.f;

    attn_prefetch_vt(sm, 0, b, 0, t);
    attn_prefetch_k(sm, b, 0, t);
    cp_commit();

    const int4* arow = (const int4*)&adjg[(size_t)(b * Nn + row0 + s_r) * Nn];

    for (int mt = 0; mt < NTILE; mt++) {
        const int buf = mt & 1;
        cp_wait<0>();
        __syncthreads();

        // ---- scores ----
        {
            const int4* ar = arow + ((mt * MT) >> 2) + s_half * 8;
#pragma unroll
            for (int i4 = 0; i4 < 8; i4++) {
                int4 a4 = ar[i4];
                int mbase = s_half * 32 + i4 * 4;
                int av[4] = {a4.x, a4.y, a4.z, a4.w};
#pragma unroll
                for (int j = 0; j < 4; j++) {
                    int m = mbase + j;
                    const float4* k4 = (const float4*)&sm.k[s_hh][m][0];
                    float s = 0.f;
#pragma unroll
                    for (int d4 = 0; d4 < 4; d4++) {
                        float4 kk = k4[d4];
                        s += qreg[4 * d4] * kk.x + qreg[4 * d4 + 1] * kk.y
                           + qreg[4 * d4 + 2] * kk.z + qreg[4 * d4 + 3] * kk.w;
                    }
                    s *= 0.25f;
                    s = (s > 0.f) ? s : 0.2f * s;
                    if (av[j] == 0) s = NEGV;
                    sm.p[s_hh][m][s_r] = s;
                }
            }
        }
        __syncthreads();

        if (mt + 1 < NTILE) {
            attn_prefetch_vt(sm, buf ^ 1, b, (mt + 1) * MT, t);
            attn_prefetch_k(sm, b, (mt + 1) * MT, t);
        }
        cp_commit();

        // ---- online softmax ----
        {
            float tmax = -INFINITY;
#pragma unroll 4
            for (int j = 0; j < 32; j++)
                tmax = fmaxf(tmax, sm.p[s_hh][s_half * 32 + j][s_r]);
            tmax = fmaxf(tmax, __shfl_xor_sync(0xffffffffu, tmax, 1));
            float oldmax = sm.rmax[s_hh][s_r];
            float nmax = fmaxf(oldmax, tmax);
            float ssum = 0.f;
#pragma unroll 4
            for (int jj = 0; jj < 16; jj++) {
                int m = s_half * 32 + 2 * jj;
                float e0 = __expf(sm.p[s_hh][m][s_r] - nmax);
                float e1 = __expf(sm.p[s_hh][m + 1][s_r] - nmax);
                ssum += e0 + e1;
                __nv_bfloat162 h2 = __floats2bfloat162_rn(e0, e1);
                __nv_bfloat162 l2 = __floats2bfloat162_rn(
                    e0 - __bfloat162float(h2.x), e1 - __bfloat162float(h2.y));
                sm.p_hi[s_hh][s_r][s_half * 16 + jj] = *reinterpret_cast<u32t*>(&h2);
                sm.p_lo[s_hh][s_r][s_half * 16 + jj] = *reinterpret_cast<u32t*>(&l2);
            }
            ssum += __shfl_xor_sync(0xffffffffu, ssum, 1);
            if (s_half == 0) {
                float f = __expf(oldmax - nmax);
                sm.fac[s_hh][s_r] = f;
                sm.rsum[s_hh][s_r] = sm.rsum[s_hh][s_r] * f + ssum;
                sm.rmax[s_hh][s_r] = nmax;
            }
        }
        __syncthreads();

        // ---- PV: bf16 mma ----
        {
            float f0 = sm.fac[m_h][ra];
            float f1 = sm.fac[m_h][rb];
#pragma unroll
            for (int n = 0; n < NT_C; n++) {
                acc[n][0] *= f0; acc[n][1] *= f0;
                acc[n][2] *= f1; acc[n][3] *= f1;
            }
            const u32t* phr = &sm.p_hi[m_h][0][0];
            const u32t* plr = &sm.p_lo[m_h][0][0];
            const u32t* vtb = &sm.vt[buf][m_h][0][0];
#pragma unroll
            for (int ks = 0; ks < 4; ks++) {
                const int pb = ks * 8;
                u32t ah0 = phr[ra * 36 + pb + tg];
                u32t ah1 = phr[rb * 36 + pb + tg];
                u32t ah2 = phr[ra * 36 + pb + tg + 4];
                u32t ah3 = phr[rb * 36 + pb + tg + 4];
                u32t al0 = plr[ra * 36 + pb + tg];
                u32t al1 = plr[rb * 36 + pb + tg];
                u32t al2 = plr[ra * 36 + pb + tg + 4];
                u32t al3 = plr[rb * 36 + pb + tg + 4];
#pragma unroll
                for (int n = 0; n < NT_C; n++) {
                    const u32t* col = vtb + (n * 8 + gid) * 68;
                    u32t bh0 = col[pb + tg];
                    u32t bh1 = col[pb + tg + 4];
                    u32t bl0 = col[32 + pb + tg];
                    u32t bl1 = col[32 + pb + tg + 4];
                    MMA_BF16(acc[n][0], acc[n][1], acc[n][2], acc[n][3],
                             ah0, ah1, ah2, ah3, bh0, bh1);
                    MMA_BF16(acc[n][0], acc[n][1], acc[n][2], acc[n][3],
                             ah0, ah1, ah2, ah3, bl0, bl1);
                    MMA_BF16(acc[n][0], acc[n][1], acc[n][2], acc[n][3],
                             al0, al1, al2, al3, bh0, bh1);
                }
            }
        }
        __syncthreads();
    }

    float inv0 = 0.5f / sm.rsum[m_h][ra];
    float inv1 = 0.5f / sm.rsum[m_h][rb];
    float* osh = (float*)&sm.vt[0][0][0][0];
    if (m_h == 0) {
#pragma unroll
        for (int n = 0; n < NT_C; n++) {
            int cbase = n * 8 + 2 * tg;
            osh[ra * VP + cbase]     = acc[n][0] * inv0;
            osh[ra * VP + cbase + 1] = acc[n][1] * inv0;
            osh[rb * VP + cbase]     = acc[n][2] * inv1;
            osh[rb * VP + cbase + 1] = acc[n][3] * inv1;
        }
    }
    __syncthreads();
    if (m_h == 1) {
#pragma unroll
        for (int n = 0; n < NT_C; n++) {
            int cbase = n * 8 + 2 * tg;
            osh[ra * VP + cbase]     += acc[n][0] * inv0;
            osh[ra * VP + cbase + 1] += acc[n][1] * inv0;
            osh[rb * VP + cbase]     += acc[n][2] * inv1;
            osh[rb * VP + cbase + 1] += acc[n][3] * inv1;
        }
    }
    __syncthreads();

    for (int idx = t; idx < RT * Cc; idx += 256) {
        int r = idx / Cc, c = idx % Cc;
        g_comb[(b * Nn + row0 + r) * VP + c] = osh[r * VP + c];
    }
}

// =================== 3a) gates r, u, cand_x (R15, unchanged) ===================
struct GateASmem {
    u32t  sel_hi[64][68];
    u32t  sel_lo[64][68];
    u32t  W_hi[2][64][68];
    u32t  W_lo[2][64][68];
    float W_s[2][64];
    float sel_s[64];
    float qv[Qq][64];
    int   nodes[64];
};

__global__ void __launch_bounds__(256, 2) gateA_kernel(
    const float* __restrict__ qv_g, const int* __restrict__ nodes,
    const float* __restrict__ x_g, const float* __restrict__ h_g,
    const float* __restrict__ b_r, const float* __restrict__ b_u,
    const float* __restrict__ b_c) {
    extern __shared__ char sm_raw[];
    GateASmem& sm = *reinterpret_cast<GateASmem*>(sm_raw);
    const int t = threadIdx.x;
    const int k0 = blockIdx.x * 64;
    const int g = blockIdx.y;
    const float* bias = (g == 0) ? b_r : (g == 1) ? b_u : b_c;
    const int KCH = (g == 2) ? 4 : 8;
    const int NP4 = KCH * 2;

    if (t < 64) sm.nodes[t] = nodes[k0 + t];
    __syncthreads();

    for (int idx = t; idx < 64 * KCH * 8; idx += 256) {
        int r = idx / (KCH * 8), kp = idx % (KCH * 8);
        float v0, v1;
        if (g == 2) {
            v0 = x_g[sm.nodes[r] * 65 + 2 * kp];
            v1 = x_g[sm.nodes[r] * 65 + 2 * kp + 1];
        } else {
            size_t base = (size_t)sm.nodes[r] * VP;
            v0 = g_comb[base + 2 * kp];
            v1 = g_comb[base + 2 * kp + 1];
        }
        __nv_bfloat162 h2 = __floats2bfloat162_rn(v0, v1);
        __nv_bfloat162 l2 = __floats2bfloat162_rn(
            v0 - __bfloat162float(h2.x), v1 - __bfloat162float(h2.y));
        sm.sel_hi[r][kp] = *reinterpret_cast<u32t*>(&h2);
        sm.sel_lo[r][kp] = *reinterpret_cast<u32t*>(&l2);
    }
    if (t < 64) {
        sm.sel_s[t] = (g == 2) ? x_g[sm.nodes[t] * 65 + 64]
                               : g_comb[(size_t)sm.nodes[t] * VP + 128];
    }
    for (int idx = t; idx < 64 * Qq; idx += 256) {
        int r = idx / Qq, q = idx % Qq;
        sm.qv[q][r] = qv_g[(k0 + r) * Qq + q];
    }
    {
        size_t gb = (size_t)(g * 16 + 0) * 64;
        for (int idx = t; idx < 64 * NP4; idx += 256) {
            int c = idx / NP4, p4 = idx % NP4;
            cp16(&sm.W_hi[0][c][p4 * 4], &g_Wt_hi[(gb + c) * 64 + p4 * 4]);
            cp16(&sm.W_lo[0][c][p4 * 4], &g_Wt_lo[(gb + c) * 64 + p4 * 4]);
        }
        for (int idx = t; idx < 16; idx += 256)
            cp16(&sm.W_s[0][idx * 4], &g_Ws[gb + idx * 4]);
    }
    cp_commit();

    const int warp = t >> 5, lane = t & 31;
    const int R0 = (warp & 3) * 16;
    const int nh = (warp >> 2) * 32;
    const int gid = lane >> 2, tg = lane & 3;
    const int ra = R0 + gid, rb = R0 + gid + 8;

    float acc[4][4];
#pragma unroll
    for (int n = 0; n < 4; n++)
#pragma unroll
        for (int j = 0; j < 4; j++) acc[n][j] = 0.f;

    for (int q = 0; q < Qq; q++) {
        const int buf = q & 1;
        if (q + 1 < Qq) {
            size_t gb = (size_t)(g * 16 + q + 1) * 64;
            for (int idx = t; idx < 64 * NP4; idx += 256) {
                int c = idx / NP4, p4 = idx % NP4;
                cp16(&sm.W_hi[buf ^ 1][c][p4 * 4], &g_Wt_hi[(gb + c) * 64 + p4 * 4]);
                cp16(&sm.W_lo[buf ^ 1][c][p4 * 4], &g_Wt_lo[(gb + c) * 64 + p4 * 4]);
            }
            for (int idx = t; idx < 16; idx += 256)
                cp16(&sm.W_s[buf ^ 1][idx * 4], &g_Ws[gb + idx * 4]);
        }
        cp_commit();
        cp_wait<1>();
        __syncthreads();

        float tmp[4][4];
#pragma unroll
        for (int n = 0; n < 4; n++)
#pragma unroll
            for (int j = 0; j < 4; j++) tmp[n][j] = 0.f;

        for (int ch = 0; ch < KCH; ch++) {
            const int pb = ch * 8;
            u32t ah0 = sm.sel_hi[ra][pb + tg];
            u32t ah1 = sm.sel_hi[rb][pb + tg];
            u32t ah2 = sm.sel_hi[ra][pb + tg + 4];
            u32t ah3 = sm.sel_hi[rb][pb + tg + 4];
            u32t al0 = sm.sel_lo[ra][pb + tg];
            u32t al1 = sm.sel_lo[rb][pb + tg];
            u32t al2 = sm.sel_lo[ra][pb + tg + 4];
            u32t al3 = sm.sel_lo[rb][pb + tg + 4];
#pragma unroll
            for (int n = 0; n < 4; n++) {
                const int col = nh + n * 8 + gid;
                u32t bh0 = sm.W_hi[buf][col][pb + tg];
                u32t bh1 = sm.W_hi[buf][col][pb + tg + 4];
                u32t bl0 = sm.W_lo[buf][col][pb + tg];
                u32t bl1 = sm.W_lo[buf][col][pb + tg + 4];
                MMA_BF16(tmp[n][0], tmp[n][1], tmp[n][2], tmp[n][3],
                         ah0, ah1, ah2, ah3, bh0, bh1);
                MMA_BF16(tmp[n][0], tmp[n][1], tmp[n][2], tmp[n][3],
                         ah0, ah1, ah2, ah3, bl0, bl1);
                MMA_BF16(tmp[n][0], tmp[n][1], tmp[n][2], tmp[n][3],
                         al0, al1, al2, al3, bh0, bh1);
            }
        }
        {
            float sa = sm.sel_s[ra], sb = sm.sel_s[rb];
#pragma unroll
            for (int n = 0; n < 4; n++) {
                int colc = nh + n * 8 + 2 * tg;
                float w0 = sm.W_s[buf][colc], w1 = sm.W_s[buf][colc + 1];
                tmp[n][0] += sa * w0; tmp[n][1] += sa * w1;
                tmp[n][2] += sb * w0; tmp[n][3] += sb * w1;
            }
        }
        float qa = sm.qv[q][ra], qb = sm.qv[q][rb];
#pragma unroll
        for (int n = 0; n < 4; n++) {
            acc[n][0] += qa * tmp[n][0]; acc[n][1] += qa * tmp[n][1];
            acc[n][2] += qb * tmp[n][2]; acc[n][3] += qb * tmp[n][3];
        }
        __syncthreads();
    }

    for (int q = 0; q < Qq; q++) {
        float qa = sm.qv[q][ra], qb = sm.qv[q][rb];
#pragma unroll
        for (int n = 0; n < 4; n++) {
            int col = nh + n * 8 + 2 * tg;
            float b0 = bias[q * 64 + col], b1 = bias[q * 64 + col + 1];
            acc[n][0] += qa * b0; acc[n][1] += qa * b1;
            acc[n][2] += qb * b0; acc[n][3] += qb * b1;
        }
    }

#pragma unroll
    for (int n = 0; n < 4; n++) {
        int col = nh + n * 8 + 2 * tg;
        int ka = k0 + ra, kb = k0 + rb;
        if (g == 0) {
            float z00 = 1.f / (1.f + __expf(-acc[n][0]));
            float z01 = 1.f / (1.f + __expf(-acc[n][1]));
            float z10 = 1.f / (1.f + __expf(-acc[n][2]));
            float z11 = 1.f / (1.f + __expf(-acc[n][3]));
            int na = sm.nodes[ra], nb = sm.nodes[rb];
            g_hsel[ka * 64 + col]     = z00 * h_g[na * 64 + col];
            g_hsel[ka * 64 + col + 1] = z01 * h_g[na * 64 + col + 1];
            g_hsel[kb * 64 + col]     = z10 * h_g[nb * 64 + col];
            g_hsel[kb * 64 + col + 1] = z11 * h_g[nb * 64 + col + 1];
        } else if (g == 1) {
            g_u[ka * 64 + col]     = 1.f / (1.f + __expf(-acc[n][0]));
            g_u[ka * 64 + col + 1] = 1.f / (1.f + __expf(-acc[n][1]));
            g_u[kb * 64 + col]     = 1.f / (1.f + __expf(-acc[n][2]));
            g_u[kb * 64 + col + 1] = 1.f / (1.f + __expf(-acc[n][3]));
        } else {
            g_cx[ka * 64 + col]     = acc[n][0];
            g_cx[ka * 64 + col + 1] = acc[n][1];
            g_cx[kb * 64 + col]     = acc[n][2];
            g_cx[kb * 64 + col + 1] = acc[n][3];
        }
    }
}

// =================== 3b) cand h-part + final combine (R15, unchanged) ===================
struct GateBSmem {
    u32t  sel_hi[64][36];
    u32t  sel_lo[64][36];
    u32t  W_hi[2][64][36];
    u32t  W_lo[2][64][36];
    float qv[Qq][64];
};

__global__ void __launch_bounds__(256, 2) gateB_kernel(
    const float* __restrict__ qv_g, float* __restrict__ out) {
    extern __shared__ char sm_raw[];
    GateBSmem& sm = *reinterpret_cast<GateBSmem*>(sm_raw);
    const int t = threadIdx.x;
    const int k0 = blockIdx.x * 64;

    for (int idx = t; idx < 64 * 32; idx += 256) {
        int r = idx >> 5, kp = idx & 31;
        float v0 = g_hsel[(k0 + r) * 64 + 2 * kp];
        float v1 = g_hsel[(k0 + r) * 64 + 2 * kp + 1];
        __nv_bfloat162 h2 = __floats2bfloat162_rn(v0, v1);
        __nv_bfloat162 l2 = __floats2bfloat162_rn(
            v0 - __bfloat162float(h2.x), v1 - __bfloat162float(h2.y));
        sm.sel_hi[r][kp] = *reinterpret_cast<u32t*>(&h2);
        sm.sel_lo[r][kp] = *reinterpret_cast<u32t*>(&l2);
    }
    for (int idx = t; idx < 64 * Qq; idx += 256) {
        int r = idx / Qq, q = idx % Qq;
        sm.qv[q][r] = qv_g[(k0 + r) * Qq + q];
    }
    {
        size_t gb = (size_t)(3 * 16 + 0) * 64;
        for (int idx = t; idx < 64 * 8; idx += 256) {
            int c = idx >> 3, p4 = idx & 7;
            cp16(&sm.W_hi[0][c][p4 * 4], &g_Wt_hi[(gb + c) * 64 + p4 * 4]);
            cp16(&sm.W_lo[0][c][p4 * 4], &g_Wt_lo[(gb + c) * 64 + p4 * 4]);
        }
    }
    cp_commit();

    const int warp = t >> 5, lane = t & 31;
    const int R0 = (warp & 3) * 16;
    const int nh = (warp >> 2) * 32;
    const int gid = lane >> 2, tg = lane & 3;
    const int ra = R0 + gid, rb = R0 + gid + 8;

    float acc[4][4];
#pragma unroll
    for (int n = 0; n < 4; n++)
#pragma unroll
        for (int j = 0; j < 4; j++) acc[n][j] = 0.f;

    for (int q = 0; q < Qq; q++) {
        const int buf = q & 1;
        if (q + 1 < Qq) {
            size_t gb = (size_t)(3 * 16 + q + 1) * 64;
            for (int idx = t; idx < 64 * 8; idx += 256) {
                int c = idx >> 3, p4 = idx & 7;
                cp16(&sm.W_hi[buf ^ 1][c][p4 * 4], &g_Wt_hi[(gb + c) * 64 + p4 * 4]);
                cp16(&sm.W_lo[buf ^ 1][c][p4 * 4], &g_Wt_lo[(gb + c) * 64 + p4 * 4]);
            }
        }
        cp_commit();
        cp_wait<1>();
        __syncthreads();

        float tmp[4][4];
#pragma unroll
        for (int n = 0; n < 4; n++)
#pragma unroll
            for (int j = 0; j < 4; j++) tmp[n][j] = 0.f;

#pragma unroll
        for (int ch = 0; ch < 4; ch++) {
            const int pb = ch * 8;
            u32t ah0 = sm.sel_hi[ra][pb + tg];
            u32t ah1 = sm.sel_hi[rb][pb + tg];
            u32t ah2 = sm.sel_hi[ra][pb + tg + 4];
            u32t ah3 = sm.sel_hi[rb][pb + tg + 4];
            u32t al0 = sm.sel_lo[ra][pb + tg];
            u32t al1 = sm.sel_lo[rb][pb + tg];
            u32t al2 = sm.sel_lo[ra][pb + tg + 4];
            u32t al3 = sm.sel_lo[rb][pb + tg + 4];
#pragma unroll
            for (int n = 0; n < 4; n++) {
                const int col = nh + n * 8 + gid;
                u32t bh0 = sm.W_hi[buf][col][pb + tg];
                u32t bh1 = sm.W_hi[buf][col][pb + tg + 4];
                u32t bl0 = sm.W_lo[buf][col][pb + tg];
                u32t bl1 = sm.W_lo[buf][col][pb + tg + 4];
                MMA_BF16(tmp[n][0], tmp[n][1], tmp[n][2], tmp[n][3],
                         ah0, ah1, ah2, ah3, bh0, bh1);
                MMA_BF16(tmp[n][0], tmp[n][1], tmp[n][2], tmp[n][3],
                         ah0, ah1, ah2, ah3, bl0, bl1);
                MMA_BF16(tmp[n][0], tmp[n][1], tmp[n][2], tmp[n][3],
                         al0, al1, al2, al3, bh0, bh1);
            }
        }
        float qa = sm.qv[q][ra], qb = sm.qv[q][rb];
#pragma unroll
        for (int n = 0; n < 4; n++) {
            acc[n][0] += qa * tmp[n][0]; acc[n][1] += qa * tmp[n][1];
            acc[n][2] += qb * tmp[n][2]; acc[n][3] += qb * tmp[n][3];
        }
        __syncthreads();
    }

#pragma unroll
    for (int n = 0; n < 4; n++) {
        int col = nh + n * 8 + 2 * tg;
        int ka = k0 + ra, kb = k0 + rb;
#pragma unroll
        for (int j = 0; j < 2; j++) {
            int o = col + j;
            float cand = tanhf(g_cx[ka * 64 + o] + acc[n][j]);
            float u = g_u[ka * 64 + o];
            float hs = g_hsel[ka * 64 + o];
            out[ka * 64 + o] = (1.f - u) * hs + u * cand;
            float cand2 = tanhf(g_cx[kb * 64 + o] + acc[n][2 + j]);
            float u2 = g_u[kb * 64 + o];
            float hs2 = g_hsel[kb * 64 + o];
            out[kb * 64 + o] = (1.f - u2) * hs2 + u2 * cand2;
        }
    }
}

// =================== launch ===================
extern "C" void kernel_launch(void* const* d_in, const int* in_sizes, int n_in,
                              void* d_out, int out_size) {
    const float* x   = (const float*)d_in[0];
    const float* h   = (const float*)d_in[1];
    const float* qv  = (const float*)d_in[2];
    const int*   adj = (const int*)d_in[3];
    const int*   nodes = (const int*)d_in[4];
    const float* Wq = (const float*)d_in[5];
    const float* bq = (const float*)d_in[6];
    const float* Wk = (const float*)d_in[7];
    const float* bk = (const float*)d_in[8];
    const float* Wv = (const float*)d_in[9];
    const float* bv = (const float*)d_in[10];
    const float* W_r = (const float*)d_in[11];
    const float* b_r = (const float*)d_in[12];
    const float* W_u = (const float*)d_in[13];
    const float* b_u = (const float*)d_in[14];
    const float* W_c = (const float*)d_in[15];
    const float* b_c = (const float*)d_in[16];
    float* out = (float*)d_out;

    cudaFuncSetAttribute(proj_kernel, cudaFuncAttributeMaxDynamicSharedMemorySize, (int)sizeof(ProjSmem));
    cudaFuncSetAttribute(attn_kernel, cudaFuncAttributeMaxDynamicSharedMemorySize, (int)sizeof(AttnSmem));
    cudaFuncSetAttribute(gateA_kernel, cudaFuncAttributeMaxDynamicSharedMemorySize, (int)sizeof(GateASmem));
    cudaFuncSetAttribute(gateB_kernel, cudaFuncAttributeMaxDynamicSharedMemorySize, (int)sizeof(GateBSmem));

    flag_zero_kernel<<<1, 256>>>();
    flag_mark_kernel<<<Kk / 256, 256>>>(nodes);
    wsplit_kernel<<<dim3(16, 4), 256>>>(W_r, W_u, W_c);
    proj_kernel<<<dim3(NROW / 128, 3), 256, sizeof(ProjSmem)>>>(x, h, Wq, bq, Wk, bk, Wv, bv);
    attn_kernel<<<dim3(Nn / RT, Bb), 256, sizeof(AttnSmem)>>>(adj);
    gateA_kernel<<<dim3(Kk / 64, 3), 256, sizeof(GateASmem)>>>(qv, nodes, x, h,
                                                               b_r, b_u, b_c);
    gateB_kernel<<<dim3(Kk / 64, 1), 256, sizeof(GateBSmem)>>>(qv, out);
}

// round 17
// speedup vs baseline: 1.5663x; 1.5663x over previous
#include <cuda_runtime.h>
#include <cuda_bf16.h>
#include <math.h>

#define Hh 2
#define Bb 8
#define Nn 2048
#define Dd 64
#define Qq 16
#define Cc 129
#define C8v 16
#define Kk 8192
#define VP 136
#define NEGV (-9.0e15f)
#define NROW (Bb*Nn)
#define RT 64
#define MT 64
#define NTILE (Nn/MT)
#define NT_C 17

typedef unsigned long long u64t;
typedef unsigned u32t;

// bf16 mma
#define MMA_BF16(c0,c1,c2,c3, a0,a1,a2,a3, b0,b1) \
    asm volatile("mma.sync.aligned.m16n8k16.row.col.f32.bf16.bf16.f32 " \
        "{%0,%1,%2,%3}, {%4,%5,%6,%7}, {%8,%9}, {%0,%1,%2,%3};" \
        : "+f"(c0), "+f"(c1), "+f"(c2), "+f"(c3) \
        : "r"(a0), "r"(a1), "r"(a2), "r"(a3), "r"(b0), "r"(b1))

// ---------------- device scratch ----------------
__device__ float g_q[Hh*NROW*C8v];
__device__ float g_k[Hh*NROW*C8v];
__device__ u32t  g_vt_hi[Hh*136*(NROW/2)];
__device__ u32t  g_vt_lo[Hh*136*(NROW/2)];
__device__ float g_comb[NROW*VP];
__device__ float g_u[Kk*Dd];
__device__ float g_hsel[Kk*Dd];
__device__ float g_cx[Kk*Dd];
__device__ int   g_batch_flag[Bb];
__device__ int   g_tile_flag[NROW/RT];
__device__ u32t  g_Wt_hi[4*16*64*64];
__device__ u32t  g_Wt_lo[4*16*64*64];
__device__ float g_Ws[4*16*64];

// ---------------- cp.async helpers ----------------
__device__ __forceinline__ unsigned smem_u32(const void* p) {
    return (unsigned)__cvta_generic_to_shared(p);
}
__device__ __forceinline__ void cp16(void* dst, const void* src) {
    asm volatile("cp.async.cg.shared.global [%0], [%1], 16;\n"
                 :: "r"(smem_u32(dst)), "l"(src));
}
__device__ __forceinline__ void cp_commit() { asm volatile("cp.async.commit_group;\n"); }
template<int N> __device__ __forceinline__ void cp_wait() {
    asm volatile("cp.async.wait_group %0;\n" :: "n"(N));
}

// ---------------- flags ----------------
__global__ void flag_zero_kernel() {
    int t = threadIdx.x;
    if (t < Bb) g_batch_flag[t] = 0;
    for (int i = t; i < NROW/RT; i += 256) g_tile_flag[i] = 0;
}
__global__ void flag_mark_kernel(const int* __restrict__ nodes) {
    int i = blockIdx.x * 256 + threadIdx.x;
    if (i < Kk) {
        int row = nodes[i];
        g_tile_flag[row >> 6] = 1;
        g_batch_flag[row >> 11] = 1;
    }
}

// ---------------- weight split ----------------
__global__ void wsplit_kernel(const float* __restrict__ W_r,
                              const float* __restrict__ W_u,
                              const float* __restrict__ W_c) {
    const int q = blockIdx.x, s = blockIdx.y, t = threadIdx.x;
    const float* W = (s == 0) ? W_r : (s == 1) ? W_u : W_c;
    const int rb0 = (s == 3) ? 65 : 0;
    const int npair = (s < 2) ? 64 : 32;
    const int srow = (s < 2) ? 128 : (s == 2) ? 64 : -1;
    for (int idx = t; idx < 64 * 64; idx += 256) {
        int o = idx >> 6, kp = idx & 63;
        float v0 = 0.f, v1 = 0.f;
        if (kp < npair) {
            int k0 = rb0 + 2 * kp;
            v0 = W[(q * Cc + k0) * 64 + o];
            v1 = W[(q * Cc + k0 + 1) * 64 + o];
        }
        __nv_bfloat162 h2 = __floats2bfloat162_rn(v0, v1);
        __nv_bfloat162 l2 = __floats2bfloat162_rn(
            v0 - __bfloat162float(h2.x), v1 - __bfloat162float(h2.y));
        size_t gi = ((size_t)(s * 16 + q) * 64 + o) * 64 + kp;
        g_Wt_hi[gi] = *reinterpret_cast<u32t*>(&h2);
        g_Wt_lo[gi] = *reinterpret_cast<u32t*>(&l2);
    }
    if (srow >= 0) {
        for (int o = t; o < 64; o += 256)
            g_Ws[(s * 16 + q) * 64 + o] = W[(q * Cc + srow) * 64 + o];
    }
}

// =================== 1) QKV projection (conflict-free warp mapping) ===================
struct ProjSmem {
    union {
        float comb[Cc][36];
        struct { __nv_bfloat16 hi[136][32]; __nv_bfloat16 lo[136][32]; } st;
    } u;
    float W[Cc][VP];
    float bias[VP];
};

__global__ void proj_kernel(const float* __restrict__ x, const float* __restrict__ h,
                            const float* __restrict__ Wq, const float* __restrict__ bq,
                            const float* __restrict__ Wk, const float* __restrict__ bk,
                            const float* __restrict__ Wv, const float* __restrict__ bv) {
    extern __shared__ char sm_raw[];
    ProjSmem& sm = *reinterpret_cast<ProjSmem*>(sm_raw);
    const int t = threadIdx.x;
    const int row0 = blockIdx.x * 32;
    if (!g_batch_flag[row0 >> 11]) return;
    const int y = blockIdx.y;

    for (int idx = t; idx < 32 * Cc; idx += 256) {
        int r = idx / Cc, c = idx % Cc;
        int row = row0 + r;
        float v = (c < 65) ? x[row * 65 + c] : h[row * 64 + (c - 65)];
        sm.u.comb[c][r] = v;
    }
    if (y == 0) {
        for (int idx = t; idx < Cc * 64; idx += 256) {
            int c = idx / 64, o = idx % 64;
            float w;
            if (o < 32)      w = Wq[((o >> 4) * Cc + c) * C8v + (o & 15)];
            else { int o2 = o - 32; w = Wk[((o2 >> 4) * Cc + c) * C8v + (o2 & 15)]; }
            sm.W[c][o] = w;
        }
        if (t < 64) {
            float b;
            if (t < 32)      b = bq[(t >> 4) * C8v + (t & 15)];
            else { int o2 = t - 32; b = bk[(o2 >> 4) * C8v + (o2 & 15)]; }
            sm.bias[t] = b;
        }
    } else {
        int hh = y - 1;
        for (int idx = t; idx < Cc * VP; idx += 256) {
            int c = idx / VP, o = idx % VP;
            sm.W[c][o] = (o < Cc) ? Wv[(hh * Cc + c) * Cc + o] : 0.f;
        }
        for (int o = t; o < VP; o += 256) sm.bias[o] = (o < Cc) ? bv[hh * Cc + o] : 0.f;
    }
    __syncthreads();

    // remapped: lane = row, warp = column group  (W reads warp-uniform, comb stride-1)
    const int r = t & 31, og = t >> 5;

    if (y == 0) {
        int c0 = og * 8;
        float acc[8];
#pragma unroll
        for (int j = 0; j < 8; j++) acc[j] = 0.f;
        for (int c = 0; c < Cc; c++) {
            float a = sm.u.comb[c][r];
#pragma unroll
            for (int j = 0; j < 8; j++) acc[j] += a * sm.W[c][c0 + j];
        }
        int row = row0 + r;
#pragma unroll
        for (int j = 0; j < 8; j++) {
            int o = c0 + j;
            float val = acc[j] + sm.bias[o];
            if (o < 32) {
                g_q[(((o >> 4) * NROW) + row) * C8v + (o & 15)] = val;
            } else {
                int o2 = o - 32;
                g_k[(((o2 >> 4) * NROW) + row) * C8v + (o2 & 15)] = val;
            }
        }
    } else {
        int hh = y - 1;
        int c0 = og * 16;
        int xcol = 128 + og;
        float acc[17];
#pragma unroll
        for (int j = 0; j < 17; j++) acc[j] = 0.f;
        for (int c = 0; c < Cc; c++) {
            float a = sm.u.comb[c][r];
#pragma unroll
            for (int j = 0; j < 16; j++) acc[j] += a * sm.W[c][c0 + j];
            acc[16] += a * sm.W[c][xcol];
        }
        __syncthreads();   // comb dead; staging aliases it
#pragma unroll
        for (int j = 0; j < 17; j++) {
            int c = (j < 16) ? (c0 + j) : xcol;
            float val = acc[j] + sm.bias[c];
            __nv_bfloat16 bh = __float2bfloat16(val);
            sm.u.st.hi[c][r] = bh;
            sm.u.st.lo[c][r] = __float2bfloat16(val - __bfloat162float(bh));
        }
        __syncthreads();
        for (int idx = t; idx < 136 * 16; idx += 256) {
            int c = idx >> 4, w = idx & 15;
            size_t gi = (size_t)(hh * 136 + c) * (NROW / 2) + (row0 >> 1) + w;
            g_vt_hi[gi] = ((const u32t*)&sm.u.st.hi[c][0])[w];
            g_vt_lo[gi] = ((const u32t*)&sm.u.st.lo[c][0])[w];
        }
    }
}

// =================== 2) attention (R15, unchanged) ===================
struct AttnSmem {
    u32t  vt[2][Hh][136][68];
    float k[Hh][MT][C8v];
    float p[Hh][MT][RT];
    u32t  p_hi[Hh][RT][36];
    u32t  p_lo[Hh][RT][36];
    float rmax[Hh][RT];
    float rsum[Hh][RT];
    float fac[Hh][RT];
};

__device__ __forceinline__ void attn_prefetch_vt(AttnSmem& sm, int buf, int b,
                                                 int m0, int t) {
    const int half = (b * Nn + m0) >> 1;
    for (int idx = t; idx < Hh * 136 * 8; idx += 256) {
        int h_ = idx / (136 * 8), rem = idx % (136 * 8), c = rem >> 3, w4 = rem & 7;
        size_t gi = (size_t)(h_ * 136 + c) * (NROW / 2) + half + w4 * 4;
        cp16(&sm.vt[buf][h_][c][w4 * 4], &g_vt_hi[gi]);
        cp16(&sm.vt[buf][h_][c][32 + w4 * 4], &g_vt_lo[gi]);
    }
}
__device__ __forceinline__ void attn_prefetch_k(AttnSmem& sm, int b, int m0, int t) {
    for (int idx = t; idx < Hh * MT * 4; idx += 256) {
        int h_ = idx / (MT * 4), rem = idx % (MT * 4), m = rem >> 2, d4 = rem & 3;
        cp16(&sm.k[h_][m][d4 * 4],
             &g_k[((h_ * NROW) + b * Nn + m0 + m) * C8v + d4 * 4]);
    }
}

__global__ void __launch_bounds__(256, 1) attn_kernel(const int* __restrict__ adjg) {
    extern __shared__ char sm_raw[];
    AttnSmem& sm = *reinterpret_cast<AttnSmem*>(sm_raw);
    const int t = threadIdx.x;
    const int b = blockIdx.y;
    const int row0 = blockIdx.x * RT;
    if (!g_tile_flag[(b * Nn + row0) >> 6]) return;

    const int s_hh = t >> 7, s_r = (t & 127) >> 1, s_half = t & 1;
    const int warp = t >> 5, lane = t & 31;
    const int m_h = warp >> 2;
    const int m_R0 = (warp & 3) * 16;
    const int gid = lane >> 2, tg = lane & 3;
    const int x_hh = t >> 6, x_r = t & 63;
    const int ra = m_R0 + gid, rb = m_R0 + gid + 8;

    float qreg[16];
    {
        const float4* qsrc = (const float4*)&g_q[((s_hh * NROW) + b * Nn + row0 + s_r) * C8v];
#pragma unroll
        for (int j = 0; j < 4; j++) {
            float4 qq = qsrc[j];
            qreg[4 * j] = qq.x; qreg[4 * j + 1] = qq.y;
            qreg[4 * j + 2] = qq.z; qreg[4 * j + 3] = qq.w;
        }
    }
    if (t < 128) { sm.rmax[x_hh][x_r] = -INFINITY; sm.rsum[x_hh][x_r] = 0.f; }

    float acc[NT_C][4];
#pragma unroll
    for (int n = 0; n < NT_C; n++)
#pragma unroll
        for (int j = 0; j < 4; j++) acc[n][j] = 0.f;

    attn_prefetch_vt(sm, 0, b, 0, t);
    attn_prefetch_k(sm, b, 0, t);
    cp_commit();

    const int4* arow = (const int4*)&adjg[(size_t)(b * Nn + row0 + s_r) * Nn];

    for (int mt = 0; mt < NTILE; mt++) {
        const int buf = mt & 1;
        cp_wait<0>();
        __syncthreads();

        {
            const int4* ar = arow + ((mt * MT) >> 2) + s_half * 8;
#pragma unroll
            for (int i4 = 0; i4 < 8; i4++) {
                int4 a4 = ar[i4];
                int mbase = s_half * 32 + i4 * 4;
                int av[4] = {a4.x, a4.y, a4.z, a4.w};
#pragma unroll
                for (int j = 0; j < 4; j++) {
                    int m = mbase + j;
                    const float4* k4 = (const float4*)&sm.k[s_hh][m][0];
                    float s = 0.f;
#pragma unroll
                    for (int d4 = 0; d4 < 4; d4++) {
                        float4 kk = k4[d4];
                        s += qreg[4 * d4] * kk.x + qreg[4 * d4 + 1] * kk.y
                           + qreg[4 * d4 + 2] * kk.z + qreg[4 * d4 + 3] * kk.w;
                    }
                    s *= 0.25f;
                    s = (s > 0.f) ? s : 0.2f * s;
                    if (av[j] == 0) s = NEGV;
                    sm.p[s_hh][m][s_r] = s;
                }
            }
        }
        __syncthreads();

        if (mt + 1 < NTILE) {
            attn_prefetch_vt(sm, buf ^ 1, b, (mt + 1) * MT, t);
            attn_prefetch_k(sm, b, (mt + 1) * MT, t);
        }
        cp_commit();

        {
            float tmax = -INFINITY;
#pragma unroll 4
            for (int j = 0; j < 32; j++)
                tmax = fmaxf(tmax, sm.p[s_hh][s_half * 32 + j][s_r]);
            tmax = fmaxf(tmax, __shfl_xor_sync(0xffffffffu, tmax, 1));
            float oldmax = sm.rmax[s_hh][s_r];
            float nmax = fmaxf(oldmax, tmax);
            float ssum = 0.f;
#pragma unroll 4
            for (int jj = 0; jj < 16; jj++) {
                int m = s_half * 32 + 2 * jj;
                float e0 = __expf(sm.p[s_hh][m][s_r] - nmax);
                float e1 = __expf(sm.p[s_hh][m + 1][s_r] - nmax);
                ssum += e0 + e1;
                __nv_bfloat162 h2 = __floats2bfloat162_rn(e0, e1);
                __nv_bfloat162 l2 = __floats2bfloat162_rn(
                    e0 - __bfloat162float(h2.x), e1 - __bfloat162float(h2.y));
                sm.p_hi[s_hh][s_r][s_half * 16 + jj] = *reinterpret_cast<u32t*>(&h2);
                sm.p_lo[s_hh][s_r][s_half * 16 + jj] = *reinterpret_cast<u32t*>(&l2);
            }
            ssum += __shfl_xor_sync(0xffffffffu, ssum, 1);
            if (s_half == 0) {
                float f = __expf(oldmax - nmax);
                sm.fac[s_hh][s_r] = f;
                sm.rsum[s_hh][s_r] = sm.rsum[s_hh][s_r] * f + ssum;
                sm.rmax[s_hh][s_r] = nmax;
            }
        }
        __syncthreads();

        {
            float f0 = sm.fac[m_h][ra];
            float f1 = sm.fac[m_h][rb];
#pragma unroll
            for (int n = 0; n < NT_C; n++) {
                acc[n][0] *= f0; acc[n][1] *= f0;
                acc[n][2] *= f1; acc[n][3] *= f1;
            }
            const u32t* phr = &sm.p_hi[m_h][0][0];
            const u32t* plr = &sm.p_lo[m_h][0][0];
            const u32t* vtb = &sm.vt[buf][m_h][0][0];
#pragma unroll
            for (int ks = 0; ks < 4; ks++) {
                const int pb = ks * 8;
                u32t ah0 = phr[ra * 36 + pb + tg];
                u32t ah1 = phr[rb * 36 + pb + tg];
                u32t ah2 = phr[ra * 36 + pb + tg + 4];
                u32t ah3 = phr[rb * 36 + pb + tg + 4];
                u32t al0 = plr[ra * 36 + pb + tg];
                u32t al1 = plr[rb * 36 + pb + tg];
                u32t al2 = plr[ra * 36 + pb + tg + 4];
                u32t al3 = plr[rb * 36 + pb + tg + 4];
#pragma unroll
                for (int n = 0; n < NT_C; n++) {
                    const u32t* col = vtb + (n * 8 + gid) * 68;
                    u32t bh0 = col[pb + tg];
                    u32t bh1 = col[pb + tg + 4];
                    u32t bl0 = col[32 + pb + tg];
                    u32t bl1 = col[32 + pb + tg + 4];
                    MMA_BF16(acc[n][0], acc[n][1], acc[n][2], acc[n][3],
                             ah0, ah1, ah2, ah3, bh0, bh1);
                    MMA_BF16(acc[n][0], acc[n][1], acc[n][2], acc[n][3],
                             ah0, ah1, ah2, ah3, bl0, bl1);
                    MMA_BF16(acc[n][0], acc[n][1], acc[n][2], acc[n][3],
                             al0, al1, al2, al3, bh0, bh1);
                }
            }
        }
        __syncthreads();
    }

    float inv0 = 0.5f / sm.rsum[m_h][ra];
    float inv1 = 0.5f / sm.rsum[m_h][rb];
    float* osh = (float*)&sm.vt[0][0][0][0];
    if (m_h == 0) {
#pragma unroll
        for (int n = 0; n < NT_C; n++) {
            int cbase = n * 8 + 2 * tg;
            osh[ra * VP + cbase]     = acc[n][0] * inv0;
            osh[ra * VP + cbase + 1] = acc[n][1] * inv0;
            osh[rb * VP + cbase]     = acc[n][2] * inv1;
            osh[rb * VP + cbase + 1] = acc[n][3] * inv1;
        }
    }
    __syncthreads();
    if (m_h == 1) {
#pragma unroll
        for (int n = 0; n < NT_C; n++) {
            int cbase = n * 8 + 2 * tg;
            osh[ra * VP + cbase]     += acc[n][0] * inv0;
            osh[ra * VP + cbase + 1] += acc[n][1] * inv0;
            osh[rb * VP + cbase]     += acc[n][2] * inv1;
            osh[rb * VP + cbase + 1] += acc[n][3] * inv1;
        }
    }
    __syncthreads();

    for (int idx = t; idx < RT * Cc; idx += 256) {
        int r = idx / Cc, c = idx % Cc;
        g_comb[(b * Nn + row0 + r) * VP + c] = osh[r * VP + c];
    }
}

// =================== 3a) gates r, u, cand_x (R15, unchanged) ===================
struct GateASmem {
    u32t  sel_hi[64][68];
    u32t  sel_lo[64][68];
    u32t  W_hi[2][64][68];
    u32t  W_lo[2][64][68];
    float W_s[2][64];
    float sel_s[64];
    float qv[Qq][64];
    int   nodes[64];
};

__global__ void __launch_bounds__(256, 2) gateA_kernel(
    const float* __restrict__ qv_g, const int* __restrict__ nodes,
    const float* __restrict__ x_g, const float* __restrict__ h_g,
    const float* __restrict__ b_r, const float* __restrict__ b_u,
    const float* __restrict__ b_c) {
    extern __shared__ char sm_raw[];
    GateASmem& sm = *reinterpret_cast<GateASmem*>(sm_raw);
    const int t = threadIdx.x;
    const int k0 = blockIdx.x * 64;
    const int g = blockIdx.y;
    const float* bias = (g == 0) ? b_r : (g == 1) ? b_u : b_c;
    const int KCH = (g == 2) ? 4 : 8;
    const int NP4 = KCH * 2;

    if (t < 64) sm.nodes[t] = nodes[k0 + t];
    __syncthreads();

    for (int idx = t; idx < 64 * KCH * 8; idx += 256) {
        int r = idx / (KCH * 8), kp = idx % (KCH * 8);
        float v0, v1;
        if (g == 2) {
            v0 = x_g[sm.nodes[r] * 65 + 2 * kp];
            v1 = x_g[sm.nodes[r] * 65 + 2 * kp + 1];
        } else {
            size_t base = (size_t)sm.nodes[r] * VP;
            v0 = g_comb[base + 2 * kp];
            v1 = g_comb[base + 2 * kp + 1];
        }
        __nv_bfloat162 h2 = __floats2bfloat162_rn(v0, v1);
        __nv_bfloat162 l2 = __floats2bfloat162_rn(
            v0 - __bfloat162float(h2.x), v1 - __bfloat162float(h2.y));
        sm.sel_hi[r][kp] = *reinterpret_cast<u32t*>(&h2);
        sm.sel_lo[r][kp] = *reinterpret_cast<u32t*>(&l2);
    }
    if (t < 64) {
        sm.sel_s[t] = (g == 2) ? x_g[sm.nodes[t] * 65 + 64]
                               : g_comb[(size_t)sm.nodes[t] * VP + 128];
    }
    for (int idx = t; idx < 64 * Qq; idx += 256) {
        int r = idx / Qq, q = idx % Qq;
        sm.qv[q][r] = qv_g[(k0 + r) * Qq + q];
    }
    {
        size_t gb = (size_t)(g * 16 + 0) * 64;
        for (int idx = t; idx < 64 * NP4; idx += 256) {
            int c = idx / NP4, p4 = idx % NP4;
            cp16(&sm.W_hi[0][c][p4 * 4], &g_Wt_hi[(gb + c) * 64 + p4 * 4]);
            cp16(&sm.W_lo[0][c][p4 * 4], &g_Wt_lo[(gb + c) * 64 + p4 * 4]);
        }
        for (int idx = t; idx < 16; idx += 256)
            cp16(&sm.W_s[0][idx * 4], &g_Ws[gb + idx * 4]);
    }
    cp_commit();

    const int warp = t >> 5, lane = t & 31;
    const int R0 = (warp & 3) * 16;
    const int nh = (warp >> 2) * 32;
    const int gid = lane >> 2, tg = lane & 3;
    const int ra = R0 + gid, rb = R0 + gid + 8;

    float acc[4][4];
#pragma unroll
    for (int n = 0; n < 4; n++)
#pragma unroll
        for (int j = 0; j < 4; j++) acc[n][j] = 0.f;

    for (int q = 0; q < Qq; q++) {
        const int buf = q & 1;
        if (q + 1 < Qq) {
            size_t gb = (size_t)(g * 16 + q + 1) * 64;
            for (int idx = t; idx < 64 * NP4; idx += 256) {
                int c = idx / NP4, p4 = idx % NP4;
                cp16(&sm.W_hi[buf ^ 1][c][p4 * 4], &g_Wt_hi[(gb + c) * 64 + p4 * 4]);
                cp16(&sm.W_lo[buf ^ 1][c][p4 * 4], &g_Wt_lo[(gb + c) * 64 + p4 * 4]);
            }
            for (int idx = t; idx < 16; idx += 256)
                cp16(&sm.W_s[buf ^ 1][idx * 4], &g_Ws[gb + idx * 4]);
        }
        cp_commit();
        cp_wait<1>();
        __syncthreads();

        float tmp[4][4];
#pragma unroll
        for (int n = 0; n < 4; n++)
#pragma unroll
            for (int j = 0; j < 4; j++) tmp[n][j] = 0.f;

        for (int ch = 0; ch < KCH; ch++) {
            const int pb = ch * 8;
            u32t ah0 = sm.sel_hi[ra][pb + tg];
            u32t ah1 = sm.sel_hi[rb][pb + tg];
            u32t ah2 = sm.sel_hi[ra][pb + tg + 4];
            u32t ah3 = sm.sel_hi[rb][pb + tg + 4];
            u32t al0 = sm.sel_lo[ra][pb + tg];
            u32t al1 = sm.sel_lo[rb][pb + tg];
            u32t al2 = sm.sel_lo[ra][pb + tg + 4];
            u32t al3 = sm.sel_lo[rb][pb + tg + 4];
#pragma unroll
            for (int n = 0; n < 4; n++) {
                const int col = nh + n * 8 + gid;
                u32t bh0 = sm.W_hi[buf][col][pb + tg];
                u32t bh1 = sm.W_hi[buf][col][pb + tg + 4];
                u32t bl0 = sm.W_lo[buf][col][pb + tg];
                u32t bl1 = sm.W_lo[buf][col][pb + tg + 4];
                MMA_BF16(tmp[n][0], tmp[n][1], tmp[n][2], tmp[n][3],
                         ah0, ah1, ah2, ah3, bh0, bh1);
                MMA_BF16(tmp[n][0], tmp[n][1], tmp[n][2], tmp[n][3],
                         ah0, ah1, ah2, ah3, bl0, bl1);
                MMA_BF16(tmp[n][0], tmp[n][1], tmp[n][2], tmp[n][3],
                         al0, al1, al2, al3, bh0, bh1);
            }
        }
        {
            float sa = sm.sel_s[ra], sb = sm.sel_s[rb];
#pragma unroll
            for (int n = 0; n < 4; n++) {
                int colc = nh + n * 8 + 2 * tg;
                float w0 = sm.W_s[buf][colc], w1 = sm.W_s[buf][colc + 1];
                tmp[n][0] += sa * w0; tmp[n][1] += sa * w1;
                tmp[n][2] += sb * w0; tmp[n][3] += sb * w1;
            }
        }
        float qa = sm.qv[q][ra], qb = sm.qv[q][rb];
#pragma unroll
        for (int n = 0; n < 4; n++) {
            acc[n][0] += qa * tmp[n][0]; acc[n][1] += qa * tmp[n][1];
            acc[n][2] += qb * tmp[n][2]; acc[n][3] += qb * tmp[n][3];
        }
        __syncthreads();
    }

    for (int q = 0; q < Qq; q++) {
        float qa = sm.qv[q][ra], qb = sm.qv[q][rb];
#pragma unroll
        for (int n = 0; n < 4; n++) {
            int col = nh + n * 8 + 2 * tg;
            float b0 = bias[q * 64 + col], b1 = bias[q * 64 + col + 1];
            acc[n][0] += qa * b0; acc[n][1] += qa * b1;
            acc[n][2] += qb * b0; acc[n][3] += qb * b1;
        }
    }

#pragma unroll
    for (int n = 0; n < 4; n++) {
        int col = nh + n * 8 + 2 * tg;
        int ka = k0 + ra, kb = k0 + rb;
        if (g == 0) {
            float z00 = 1.f / (1.f + __expf(-acc[n][0]));
            float z01 = 1.f / (1.f + __expf(-acc[n][1]));
            float z10 = 1.f / (1.f + __expf(-acc[n][2]));
            float z11 = 1.f / (1.f + __expf(-acc[n][3]));
            int na = sm.nodes[ra], nb = sm.nodes[rb];
            g_hsel[ka * 64 + col]     = z00 * h_g[na * 64 + col];
            g_hsel[ka * 64 + col + 1] = z01 * h_g[na * 64 + col + 1];
            g_hsel[kb * 64 + col]     = z10 * h_g[nb * 64 + col];
            g_hsel[kb * 64 + col + 1] = z11 * h_g[nb * 64 + col + 1];
        } else if (g == 1) {
            g_u[ka * 64 + col]     = 1.f / (1.f + __expf(-acc[n][0]));
            g_u[ka * 64 + col + 1] = 1.f / (1.f + __expf(-acc[n][1]));
            g_u[kb * 64 + col]     = 1.f / (1.f + __expf(-acc[n][2]));
            g_u[kb * 64 + col + 1] = 1.f / (1.f + __expf(-acc[n][3]));
        } else {
            g_cx[ka * 64 + col]     = acc[n][0];
            g_cx[ka * 64 + col + 1] = acc[n][1];
            g_cx[kb * 64 + col]     = acc[n][2];
            g_cx[kb * 64 + col + 1] = acc[n][3];
        }
    }
}

// =================== 3b) cand h-part + final combine (R15, unchanged) ===================
struct GateBSmem {
    u32t  sel_hi[64][36];
    u32t  sel_lo[64][36];
    u32t  W_hi[2][64][36];
    u32t  W_lo[2][64][36];
    float qv[Qq][64];
};

__global__ void __launch_bounds__(256, 2) gateB_kernel(
    const float* __restrict__ qv_g, float* __restrict__ out) {
    extern __shared__ char sm_raw[];
    GateBSmem& sm = *reinterpret_cast<GateBSmem*>(sm_raw);
    const int t = threadIdx.x;
    const int k0 = blockIdx.x * 64;

    for (int idx = t; idx < 64 * 32; idx += 256) {
        int r = idx >> 5, kp = idx & 31;
        float v0 = g_hsel[(k0 + r) * 64 + 2 * kp];
        float v1 = g_hsel[(k0 + r) * 64 + 2 * kp + 1];
        __nv_bfloat162 h2 = __floats2bfloat162_rn(v0, v1);
        __nv_bfloat162 l2 = __floats2bfloat162_rn(
            v0 - __bfloat162float(h2.x), v1 - __bfloat162float(h2.y));
        sm.sel_hi[r][kp] = *reinterpret_cast<u32t*>(&h2);
        sm.sel_lo[r][kp] = *reinterpret_cast<u32t*>(&l2);
    }
    for (int idx = t; idx < 64 * Qq; idx += 256) {
        int r = idx / Qq, q = idx % Qq;
        sm.qv[q][r] = qv_g[(k0 + r) * Qq + q];
    }
    {
        size_t gb = (size_t)(3 * 16 + 0) * 64;
        for (int idx = t; idx < 64 * 8; idx += 256) {
            int c = idx >> 3, p4 = idx & 7;
            cp16(&sm.W_hi[0][c][p4 * 4], &g_Wt_hi[(gb + c) * 64 + p4 * 4]);
            cp16(&sm.W_lo[0][c][p4 * 4], &g_Wt_lo[(gb + c) * 64 + p4 * 4]);
        }
    }
    cp_commit();

    const int warp = t >> 5, lane = t & 31;
    const int R0 = (warp & 3) * 16;
    const int nh = (warp >> 2) * 32;
    const int gid = lane >> 2, tg = lane & 3;
    const int ra = R0 + gid, rb = R0 + gid + 8;

    float acc[4][4];
#pragma unroll
    for (int n = 0; n < 4; n++)
#pragma unroll
        for (int j = 0; j < 4; j++) acc[n][j] = 0.f;

    for (int q = 0; q < Qq; q++) {
        const int buf = q & 1;
        if (q + 1 < Qq) {
            size_t gb = (size_t)(3 * 16 + q + 1) * 64;
            for (int idx = t; idx < 64 * 8; idx += 256) {
                int c = idx >> 3, p4 = idx & 7;
                cp16(&sm.W_hi[buf ^ 1][c][p4 * 4], &g_Wt_hi[(gb + c) * 64 + p4 * 4]);
                cp16(&sm.W_lo[buf ^ 1][c][p4 * 4], &g_Wt_lo[(gb + c) * 64 + p4 * 4]);
            }
        }
        cp_commit();
        cp_wait<1>();
        __syncthreads();

        float tmp[4][4];
#pragma unroll
        for (int n = 0; n < 4; n++)
#pragma unroll
            for (int j = 0; j < 4; j++) tmp[n][j] = 0.f;

#pragma unroll
        for (int ch = 0; ch < 4; ch++) {
            const int pb = ch * 8;
            u32t ah0 = sm.sel_hi[ra][pb + tg];
            u32t ah1 = sm.sel_hi[rb][pb + tg];
            u32t ah2 = sm.sel_hi[ra][pb + tg + 4];
            u32t ah3 = sm.sel_hi[rb][pb + tg + 4];
            u32t al0 = sm.sel_lo[ra][pb + tg];
            u32t al1 = sm.sel_lo[rb][pb + tg];
            u32t al2 = sm.sel_lo[ra][pb + tg + 4];
            u32t al3 = sm.sel_lo[rb][pb + tg + 4];
#pragma unroll
            for (int n = 0; n < 4; n++) {
                const int col = nh + n * 8 + gid;
                u32t bh0 = sm.W_hi[buf][col][pb + tg];
                u32t bh1 = sm.W_hi[buf][col][pb + tg + 4];
                u32t bl0 = sm.W_lo[buf][col][pb + tg];
                u32t bl1 = sm.W_lo[buf][col][pb + tg + 4];
                MMA_BF16(tmp[n][0], tmp[n][1], tmp[n][2], tmp[n][3],
                         ah0, ah1, ah2, ah3, bh0, bh1);
                MMA_BF16(tmp[n][0], tmp[n][1], tmp[n][2], tmp[n][3],
                         ah0, ah1, ah2, ah3, bl0, bl1);
                MMA_BF16(tmp[n][0], tmp[n][1], tmp[n][2], tmp[n][3],
                         al0, al1, al2, al3, bh0, bh1);
            }
        }
        float qa = sm.qv[q][ra], qb = sm.qv[q][rb];
#pragma unroll
        for (int n = 0; n < 4; n++) {
            acc[n][0] += qa * tmp[n][0]; acc[n][1] += qa * tmp[n][1];
            acc[n][2] += qb * tmp[n][2]; acc[n][3] += qb * tmp[n][3];
        }
        __syncthreads();
    }

#pragma unroll
    for (int n = 0; n < 4; n++) {
        int col = nh + n * 8 + 2 * tg;
        int ka = k0 + ra, kb = k0 + rb;
#pragma unroll
        for (int j = 0; j < 2; j++) {
            int o = col + j;
            float cand = tanhf(g_cx[ka * 64 + o] + acc[n][j]);
            float u = g_u[ka * 64 + o];
            float hs = g_hsel[ka * 64 + o];
            out[ka * 64 + o] = (1.f - u) * hs + u * cand;
            float cand2 = tanhf(g_cx[kb * 64 + o] + acc[n][2 + j]);
            float u2 = g_u[kb * 64 + o];
            float hs2 = g_hsel[kb * 64 + o];
            out[kb * 64 + o] = (1.f - u2) * hs2 + u2 * cand2;
        }
    }
}

// =================== launch ===================
extern "C" void kernel_launch(void* const* d_in, const int* in_sizes, int n_in,
                              void* d_out, int out_size) {
    const float* x   = (const float*)d_in[0];
    const float* h   = (const float*)d_in[1];
    const float* qv  = (const float*)d_in[2];
    const int*   adj = (const int*)d_in[3];
    const int*   nodes = (const int*)d_in[4];
    const float* Wq = (const float*)d_in[5];
    const float* bq = (const float*)d_in[6];
    const float* Wk = (const float*)d_in[7];
    const float* bk = (const float*)d_in[8];
    const float* Wv = (const float*)d_in[9];
    const float* bv = (const float*)d_in[10];
    const float* W_r = (const float*)d_in[11];
    const float* b_r = (const float*)d_in[12];
    const float* W_u = (const float*)d_in[13];
    const float* b_u = (const float*)d_in[14];
    const float* W_c = (const float*)d_in[15];
    const float* b_c = (const float*)d_in[16];
    float* out = (float*)d_out;

    cudaFuncSetAttribute(proj_kernel, cudaFuncAttributeMaxDynamicSharedMemorySize, (int)sizeof(ProjSmem));
    cudaFuncSetAttribute(attn_kernel, cudaFuncAttributeMaxDynamicSharedMemorySize, (int)sizeof(AttnSmem));
    cudaFuncSetAttribute(gateA_kernel, cudaFuncAttributeMaxDynamicSharedMemorySize, (int)sizeof(GateASmem));
    cudaFuncSetAttribute(gateB_kernel, cudaFuncAttributeMaxDynamicSharedMemorySize, (int)sizeof(GateBSmem));

    flag_zero_kernel<<<1, 256>>>();
    flag_mark_kernel<<<Kk / 256, 256>>>(nodes);
    wsplit_kernel<<<dim3(16, 4), 256>>>(W_r, W_u, W_c);
    proj_kernel<<<dim3(NROW / 32, 3), 256, sizeof(ProjSmem)>>>(x, h, Wq, bq, Wk, bk, Wv, bv);
    attn_kernel<<<dim3(Nn / RT, Bb), 256, sizeof(AttnSmem)>>>(adj);
    gateA_kernel<<<dim3(Kk / 64, 3), 256, sizeof(GateASmem)>>>(qv, nodes, x, h,
                                                               b_r, b_u, b_c);
    gateB_kernel<<<dim3(Kk / 64, 1), 256, sizeof(GateBSmem)>>>(qv, out);
}